// round 11
// baseline (speedup 1.0000x reference)
#include <cuda_runtime.h>

#define NB 64
#define NC 3
#define NH 256
#define NW 256
#define RPB 16                      // rows per block
#define KR 4                        // rows per thread

struct AugParams {
    int   doTrans, doFlip, doCut;
    int   tw, th_off;               // th_off = trans_h + 1
    int   cx0, cx1, cy0, cySpan;
    float cm, ad;                   // val = fma(x, cm, ad)
};

__global__ __launch_bounds__(256)
void diffaug_kernel(const float* __restrict__ x,
                    const float* __restrict__ p_,
                    const float* __restrict__ flip_u,
                    const float* __restrict__ bright_n,
                    const float* __restrict__ bright_u,
                    const float* __restrict__ contrast_n,
                    const float* __restrict__ contrast_u,
                    const int*   __restrict__ trans_h,
                    const int*   __restrict__ trans_w,
                    const float* __restrict__ trans_u,
                    const int*   __restrict__ cut_ox,
                    const int*   __restrict__ cut_oy,
                    const float* __restrict__ cut_u,
                    float* __restrict__ out)
{
    __shared__ AugParams P;
    // 16B-aligned; row stride 288*4B = 1152B is a 16B multiple.
    __shared__ __align__(16) float s[RPB][288]; // [0:16) left halo, [16:272) row, [272:288) right halo

    const int blk  = blockIdx.x;
    const int b    = blk / (NC * (NH / RPB));
    const int rem  = blk % (NC * (NH / RPB));
    const int c    = rem / (NH / RPB);
    const int slab = rem % (NH / RPB);
    const int h0   = slab * RPB;

    if (threadIdx.x == 0) {
        const float p = p_[0];
        const float ba = (bright_u[b] < p) ? bright_n[b] * 0.2f : 0.0f;
        const float cm = (contrast_u[b] < p) ? exp2f(contrast_n[b] * 0.5f) : 1.0f;
        P.cm      = cm;
        P.ad      = ba * cm;
        P.doFlip  = flip_u[b] < 0.5f * p;
        P.doTrans = trans_u[b] < p;
        P.th_off  = trans_h[b] + 1;
        P.tw      = trans_w[b];
        P.doCut   = cut_u[b] < p;
        const int ox = cut_ox[b], oy = cut_oy[b];
        P.cx0 = max(0, ox - 64); P.cx1 = min(NH - 1, ox + 63);
        P.cy0 = max(0, oy - 64);
        P.cySpan = min(NW - 1, oy + 63) - P.cy0;
    }
    __syncthreads();

    const int rg = (int)(threadIdx.x >> 6);        // 0..3 row group
    const int t  = (int)(threadIdx.x & 63);        // 0..63
    const int j4 = 4 * t;

    const size_t plane = (size_t)(b * NC + c) * (NH * NW);
    const float* xpl = x + plane;
    float*       opl = out + plane;

    const float cm = P.cm, ad = P.ad;
    const int   cy0 = P.cy0, cySpan = P.cySpan;
    const int   gj  = P.doFlip ? (252 - j4) : j4;
    const bool  flip = P.doFlip;
    const int   rcx0 = P.doCut ? P.cx0 : (NH + 1); // empty range if !doCut
    const int   rcx1 = P.doCut ? P.cx1 : -1;

    if (!P.doTrans) {
        // ---------- Path A: vectorized copy (+optional mirror), MLP=4 ----------
        float4 v[KR];
#pragma unroll
        for (int k = 0; k < KR; k++) {
            v[k] = *reinterpret_cast<const float4*>(xpl + (size_t)(h0 + rg + 4 * k) * NW + gj);
        }
#pragma unroll
        for (int k = 0; k < KR; k++) {
            const int h = h0 + rg + 4 * k;
            float a0, a1, a2, a3;
            if (flip) { a0 = v[k].w; a1 = v[k].z; a2 = v[k].y; a3 = v[k].x; }
            else      { a0 = v[k].x; a1 = v[k].y; a2 = v[k].z; a3 = v[k].w; }
            a0 = fmaf(a0, cm, ad); a1 = fmaf(a1, cm, ad);
            a2 = fmaf(a2, cm, ad); a3 = fmaf(a3, cm, ad);
            if (h >= rcx0 && h <= rcx1) {
                if ((unsigned)(j4     - cy0) <= (unsigned)cySpan) a0 = 0.0f;
                if ((unsigned)(j4 + 1 - cy0) <= (unsigned)cySpan) a1 = 0.0f;
                if ((unsigned)(j4 + 2 - cy0) <= (unsigned)cySpan) a2 = 0.0f;
                if ((unsigned)(j4 + 3 - cy0) <= (unsigned)cySpan) a3 = 0.0f;
            }
            *reinterpret_cast<float4*>(opl + (size_t)h * NW + j4) =
                make_float4(a0, a1, a2, a3);
        }
        return;
    }

    // ---------- Path B: translation via SMEM-staged rows with wrap halo ----------
    unsigned padMask = 0;
#pragma unroll
    for (int k = 0; k < KR; k++) {
        int gh = (h0 + rg + 4 * k) + P.th_off;
        gh = min(max(gh, 0), NH + 1);
        const bool pad = (gh == 0) || (gh == NH + 1);
        padMask |= (unsigned)pad << k;
        const int srcH = min(max(gh - 1, 0), NH - 1);
        if (!pad) {
            const float4 v = *reinterpret_cast<const float4*>(xpl + (size_t)srcH * NW + gj);
            float4 w4;
            if (flip) { w4.x = v.w; w4.y = v.z; w4.z = v.y; w4.w = v.x; }
            else      { w4 = v; }
            *reinterpret_cast<float4*>(&s[rg + 4 * k][16 + j4]) = w4;
        }
    }
    __syncthreads();

    // halo: right 17 (frow[0..16] -> s[271..287]); left 16 (frow[239..254] -> s[0..15])
    for (int idx = (int)threadIdx.x; idx < RPB * 33; idx += 256) {
        const int r = idx / 33;
        const int q = idx % 33;
        if (q < 17) s[r][271 + q] = s[r][16 + q];
        else        s[r][q - 17]  = s[r][255 + (q - 17)];
    }
    __syncthreads();

    // Gather: out[j4..j4+3] = s[16 + tw + j4 .. +3], via aligned LDS.128 pair +
    // block-uniform component select. A0 = 16+tw-r is 4-float aligned.
    const int r  = P.tw & 3;
    const int A0 = 16 + P.tw - r;

#pragma unroll
    for (int k = 0; k < KR; k++) {
        const int h = h0 + rg + 4 * k;
        float* __restrict__ op4 = opl + (size_t)h * NW + j4;
        if ((padMask >> k) & 1u) {
            *reinterpret_cast<float4*>(op4) = make_float4(0.f, 0.f, 0.f, 0.f);
            continue;
        }
        const float* srow = s[rg + 4 * k];
        const float4 f0 = *reinterpret_cast<const float4*>(srow + A0 + j4);
        float a0, a1, a2, a3;
        if (r == 0) {
            a0 = f0.x; a1 = f0.y; a2 = f0.z; a3 = f0.w;
        } else {
            const float4 f1 = *reinterpret_cast<const float4*>(srow + A0 + j4 + 4);
            if (r == 1)      { a0 = f0.y; a1 = f0.z; a2 = f0.w; a3 = f1.x; }
            else if (r == 2) { a0 = f0.z; a1 = f0.w; a2 = f1.x; a3 = f1.y; }
            else             { a0 = f0.w; a1 = f1.x; a2 = f1.y; a3 = f1.z; }
        }
        a0 = fmaf(a0, cm, ad); a1 = fmaf(a1, cm, ad);
        a2 = fmaf(a2, cm, ad); a3 = fmaf(a3, cm, ad);
        if (h >= rcx0 && h <= rcx1) {
            if ((unsigned)(j4     - cy0) <= (unsigned)cySpan) a0 = 0.0f;
            if ((unsigned)(j4 + 1 - cy0) <= (unsigned)cySpan) a1 = 0.0f;
            if ((unsigned)(j4 + 2 - cy0) <= (unsigned)cySpan) a2 = 0.0f;
            if ((unsigned)(j4 + 3 - cy0) <= (unsigned)cySpan) a3 = 0.0f;
        }
        *reinterpret_cast<float4*>(op4) = make_float4(a0, a1, a2, a3);
    }
}

extern "C" void kernel_launch(void* const* d_in, const int* in_sizes, int n_in,
                              void* d_out, int out_size)
{
    (void)in_sizes; (void)n_in; (void)out_size;
    const float* x          = (const float*)d_in[0];
    const float* p          = (const float*)d_in[1];
    const float* flip_u     = (const float*)d_in[2];
    const float* bright_n   = (const float*)d_in[3];
    const float* bright_u   = (const float*)d_in[4];
    const float* contrast_n = (const float*)d_in[5];
    const float* contrast_u = (const float*)d_in[6];
    const int*   trans_h    = (const int*)d_in[7];
    const int*   trans_w    = (const int*)d_in[8];
    const float* trans_u    = (const float*)d_in[9];
    const int*   cut_ox     = (const int*)d_in[10];
    const int*   cut_oy     = (const int*)d_in[11];
    const float* cut_u      = (const float*)d_in[12];
    float*       out        = (float*)d_out;

    const dim3 grid(NB * NC * (NH / RPB));
    const dim3 block(256);
    diffaug_kernel<<<grid, block>>>(x, p, flip_u, bright_n, bright_u,
                                    contrast_n, contrast_u, trans_h, trans_w,
                                    trans_u, cut_ox, cut_oy, cut_u, out);
}

// round 12
// speedup vs baseline: 1.0684x; 1.0684x over previous
#include <cuda_runtime.h>

#define NB 64
#define NC 3
#define NH 256
#define NW 256
#define RPB 32                      // rows per block
#define KR 8                        // rows per thread

struct AugParams {
    int   doTrans, doFlip, doCut;
    int   tw, th_off;               // th_off = trans_h + 1
    int   cx0, cx1, cy0, cySpan;
    float cm, ad;                   // val = fma(x, cm, ad)
};

__global__ __launch_bounds__(256)
void diffaug_kernel(const float* __restrict__ x,
                    const float* __restrict__ p_,
                    const float* __restrict__ flip_u,
                    const float* __restrict__ bright_n,
                    const float* __restrict__ bright_u,
                    const float* __restrict__ contrast_n,
                    const float* __restrict__ contrast_u,
                    const int*   __restrict__ trans_h,
                    const int*   __restrict__ trans_w,
                    const float* __restrict__ trans_u,
                    const int*   __restrict__ cut_ox,
                    const int*   __restrict__ cut_oy,
                    const float* __restrict__ cut_u,
                    float* __restrict__ out)
{
    __shared__ AugParams P;
    // 16B-aligned; row stride 288*4B = 1152B is a 16B multiple.
    __shared__ __align__(16) float s[RPB][288]; // [0:16) halo, [16:272) row, [272:288) halo

    const int blk  = blockIdx.x;
    const int b    = blk / (NC * (NH / RPB));
    const int rem  = blk % (NC * (NH / RPB));
    const int c    = rem / (NH / RPB);
    const int slab = rem % (NH / RPB);
    const int h0   = slab * RPB;

    if (threadIdx.x == 0) {
        const float p = p_[0];
        const float ba = (bright_u[b] < p) ? bright_n[b] * 0.2f : 0.0f;
        const float cm = (contrast_u[b] < p) ? exp2f(contrast_n[b] * 0.5f) : 1.0f;
        P.cm      = cm;
        P.ad      = ba * cm;
        P.doFlip  = flip_u[b] < 0.5f * p;
        P.doTrans = trans_u[b] < p;
        P.th_off  = trans_h[b] + 1;
        P.tw      = trans_w[b];
        P.doCut   = cut_u[b] < p;
        const int ox = cut_ox[b], oy = cut_oy[b];
        P.cx0 = max(0, ox - 64); P.cx1 = min(NH - 1, ox + 63);
        P.cy0 = max(0, oy - 64);
        P.cySpan = min(NW - 1, oy + 63) - P.cy0;
    }
    __syncthreads();

    const int rg = (int)(threadIdx.x >> 6);        // 0..3 row group
    const int t  = (int)(threadIdx.x & 63);        // 0..63
    const int j4 = 4 * t;

    const size_t plane = (size_t)(b * NC + c) * (NH * NW);
    const float* xpl = x + plane;
    float*       opl = out + plane;

    const float cm = P.cm, ad = P.ad;
    const int   cy0 = P.cy0, cySpan = P.cySpan;
    const int   gj  = P.doFlip ? (252 - j4) : j4;
    const bool  flip = P.doFlip;
    const int   rcx0 = P.doCut ? P.cx0 : (NH + 1); // empty range if !doCut
    const int   rcx1 = P.doCut ? P.cx1 : -1;

    if (!P.doTrans) {
        // ---------- Path A: vectorized copy (+optional mirror), 2 groups of MLP=4 ----------
#pragma unroll
        for (int g = 0; g < KR / 4; g++) {
            float4 v[4];
#pragma unroll
            for (int k = 0; k < 4; k++) {
                const int h = h0 + rg + 4 * (4 * g + k);
                v[k] = *reinterpret_cast<const float4*>(xpl + (size_t)h * NW + gj);
            }
#pragma unroll
            for (int k = 0; k < 4; k++) {
                const int h = h0 + rg + 4 * (4 * g + k);
                float a0, a1, a2, a3;
                if (flip) { a0 = v[k].w; a1 = v[k].z; a2 = v[k].y; a3 = v[k].x; }
                else      { a0 = v[k].x; a1 = v[k].y; a2 = v[k].z; a3 = v[k].w; }
                a0 = fmaf(a0, cm, ad); a1 = fmaf(a1, cm, ad);
                a2 = fmaf(a2, cm, ad); a3 = fmaf(a3, cm, ad);
                if (h >= rcx0 && h <= rcx1) {
                    if ((unsigned)(j4     - cy0) <= (unsigned)cySpan) a0 = 0.0f;
                    if ((unsigned)(j4 + 1 - cy0) <= (unsigned)cySpan) a1 = 0.0f;
                    if ((unsigned)(j4 + 2 - cy0) <= (unsigned)cySpan) a2 = 0.0f;
                    if ((unsigned)(j4 + 3 - cy0) <= (unsigned)cySpan) a3 = 0.0f;
                }
                *reinterpret_cast<float4*>(opl + (size_t)h * NW + j4) =
                    make_float4(a0, a1, a2, a3);
            }
        }
        return;
    }

    // ---------- Path B: translation via SMEM-staged rows with wrap halo ----------
    unsigned padMask = 0;
#pragma unroll
    for (int k = 0; k < KR; k++) {
        int gh = (h0 + rg + 4 * k) + P.th_off;
        gh = min(max(gh, 0), NH + 1);
        const bool pad = (gh == 0) || (gh == NH + 1);
        padMask |= (unsigned)pad << k;
        const int srcH = min(max(gh - 1, 0), NH - 1);
        if (!pad) {
            const float4 v = *reinterpret_cast<const float4*>(xpl + (size_t)srcH * NW + gj);
            float4 w4;
            if (flip) { w4.x = v.w; w4.y = v.z; w4.z = v.y; w4.w = v.x; }
            else      { w4 = v; }
            *reinterpret_cast<float4*>(&s[rg + 4 * k][16 + j4]) = w4;
        }
    }
    __syncthreads();

    // halo: right 17 (frow[0..16] -> s[271..287]); left 16 (frow[239..254] -> s[0..15])
    for (int idx = (int)threadIdx.x; idx < RPB * 33; idx += 256) {
        const int r = idx / 33;
        const int q = idx % 33;
        if (q < 17) s[r][271 + q] = s[r][16 + q];
        else        s[r][q - 17]  = s[r][255 + (q - 17)];
    }
    __syncthreads();

    const int base = 16 + P.tw + t;                // in-range for all accesses
#pragma unroll
    for (int k = 0; k < KR; k++) {
        const int h = h0 + rg + 4 * k;
        float* orow = opl + (size_t)h * NW;
        if ((padMask >> k) & 1u) {
#pragma unroll
            for (int i = 0; i < 4; i++) orow[t + 64 * i] = 0.0f;
            continue;
        }
        const bool rowInCut = (h >= rcx0) && (h <= rcx1);
#pragma unroll
        for (int i = 0; i < 4; i++) {
            const int w = t + 64 * i;
            float val = fmaf(s[rg + 4 * k][base + 64 * i], cm, ad);
            if (rowInCut && (unsigned)(w - cy0) <= (unsigned)cySpan) val = 0.0f;
            orow[w] = val;
        }
    }
}

extern "C" void kernel_launch(void* const* d_in, const int* in_sizes, int n_in,
                              void* d_out, int out_size)
{
    (void)in_sizes; (void)n_in; (void)out_size;
    const float* x          = (const float*)d_in[0];
    const float* p          = (const float*)d_in[1];
    const float* flip_u     = (const float*)d_in[2];
    const float* bright_n   = (const float*)d_in[3];
    const float* bright_u   = (const float*)d_in[4];
    const float* contrast_n = (const float*)d_in[5];
    const float* contrast_u = (const float*)d_in[6];
    const int*   trans_h    = (const int*)d_in[7];
    const int*   trans_w    = (const int*)d_in[8];
    const float* trans_u    = (const float*)d_in[9];
    const int*   cut_ox     = (const int*)d_in[10];
    const int*   cut_oy     = (const int*)d_in[11];
    const float* cut_u      = (const float*)d_in[12];
    float*       out        = (float*)d_out;

    const dim3 grid(NB * NC * (NH / RPB));
    const dim3 block(256);
    diffaug_kernel<<<grid, block>>>(x, p, flip_u, bright_n, bright_u,
                                    contrast_n, contrast_u, trans_h, trans_w,
                                    trans_u, cut_ox, cut_oy, cut_u, out);
}

// round 14
// speedup vs baseline: 1.0978x; 1.0274x over previous
#include <cuda_runtime.h>
#include <cstdint>

#define NB 64
#define NC 3
#define NH 256
#define NW 256
#define RPB 16                      // rows per block
#define KR 4                        // rows per thread

__device__ __forceinline__ void cpasync16(unsigned saddr, const void* gptr) {
    asm volatile("cp.async.cg.shared.global [%0], [%1], 16;\n" :: "r"(saddr), "l"(gptr));
}

__global__ __launch_bounds__(256)
void diffaug_kernel(const float* __restrict__ x,
                    const float* __restrict__ p_,
                    const float* __restrict__ flip_u,
                    const float* __restrict__ bright_n,
                    const float* __restrict__ bright_u,
                    const float* __restrict__ contrast_n,
                    const float* __restrict__ contrast_u,
                    const int*   __restrict__ trans_h,
                    const int*   __restrict__ trans_w,
                    const float* __restrict__ trans_u,
                    const int*   __restrict__ cut_ox,
                    const int*   __restrict__ cut_oy,
                    const float* __restrict__ cut_u,
                    float* __restrict__ out)
{
    __shared__ __align__(16) float s[RPB][256];   // raw (unflipped) staged rows

    const int blk  = blockIdx.x;
    const int b    = blk / (NC * (NH / RPB));
    const int rem  = blk % (NC * (NH / RPB));
    const int c    = rem / (NH / RPB);
    const int slab = rem % (NH / RPB);
    const int h0   = slab * RPB;

    // ---- per-batch params, loaded uniformly by every thread (no barrier) ----
    const float p    = __ldg(p_);
    const bool  flip = __ldg(flip_u + b) < 0.5f * p;
    const float ba   = (__ldg(bright_u  + b) < p) ? __ldg(bright_n  + b) * 0.2f : 0.0f;
    const float cm   = (__ldg(contrast_u + b) < p) ? exp2f(__ldg(contrast_n + b) * 0.5f) : 1.0f;
    const float ad   = ba * cm;
    const bool  doTrans = __ldg(trans_u + b) < p;
    const int   th_off  = __ldg(trans_h + b) + 1;
    const int   tw      = __ldg(trans_w + b);
    const bool  doCut   = __ldg(cut_u + b) < p;
    const int   ox = __ldg(cut_ox + b), oy = __ldg(cut_oy + b);
    const int   rcx0 = doCut ? max(0, ox - 64)      : (NH + 1);
    const int   rcx1 = doCut ? min(NH - 1, ox + 63) : -1;
    const int   cy0  = max(0, oy - 64);
    const int   cySpan = min(NW - 1, oy + 63) - cy0;

    const int rg = (int)(threadIdx.x >> 6);        // 0..3 row group
    const int t  = (int)(threadIdx.x & 63);        // 0..63
    const int j4 = 4 * t;

    const size_t plane = (size_t)(b * NC + c) * (NH * NW);
    const float* xpl = x + plane;
    float*       opl = out + plane;

    const int gj = flip ? (252 - j4) : j4;

    if (!doTrans) {
        // ---------- Path A: barrier-free vectorized copy (+optional mirror), MLP=4 ----------
        float4 v[KR];
#pragma unroll
        for (int k = 0; k < KR; k++) {
            v[k] = *reinterpret_cast<const float4*>(xpl + (size_t)(h0 + rg + 4 * k) * NW + gj);
        }
#pragma unroll
        for (int k = 0; k < KR; k++) {
            const int h = h0 + rg + 4 * k;
            float a0, a1, a2, a3;
            if (flip) { a0 = v[k].w; a1 = v[k].z; a2 = v[k].y; a3 = v[k].x; }
            else      { a0 = v[k].x; a1 = v[k].y; a2 = v[k].z; a3 = v[k].w; }
            a0 = fmaf(a0, cm, ad); a1 = fmaf(a1, cm, ad);
            a2 = fmaf(a2, cm, ad); a3 = fmaf(a3, cm, ad);
            if (h >= rcx0 && h <= rcx1) {
                if ((unsigned)(j4     - cy0) <= (unsigned)cySpan) a0 = 0.0f;
                if ((unsigned)(j4 + 1 - cy0) <= (unsigned)cySpan) a1 = 0.0f;
                if ((unsigned)(j4 + 2 - cy0) <= (unsigned)cySpan) a2 = 0.0f;
                if ((unsigned)(j4 + 3 - cy0) <= (unsigned)cySpan) a3 = 0.0f;
            }
            *reinterpret_cast<float4*>(opl + (size_t)h * NW + j4) =
                make_float4(a0, a1, a2, a3);
        }
        return;
    }

    // ---------- Path B: raw cp.async staging, single barrier, wrap+flip in consumer ----------
    unsigned padMask = 0;
#pragma unroll
    for (int k = 0; k < KR; k++) {
        int gh = (h0 + rg + 4 * k) + th_off;
        gh = min(max(gh, 0), NH + 1);
        const bool pad = (gh == 0) || (gh == NH + 1);
        padMask |= (unsigned)pad << k;
        const int srcH = min(max(gh - 1, 0), NH - 1);
        if (!pad) {
            const unsigned saddr =
                (unsigned)__cvta_generic_to_shared(&s[rg + 4 * k][j4]);
            cpasync16(saddr, xpl + (size_t)srcH * NW + j4);
        }
    }
    asm volatile("cp.async.commit_group;\n");
    asm volatile("cp.async.wait_group 0;\n" ::: "memory");
    __syncthreads();

    // consumer: out[w] = x_raw[255 - gw] if flip else x_raw[gw], gw=(w+tw) mod 255
    const int flipOff  = flip ? 255 : 0;
    const int flipSign = flip ? -1 : 1;
    const int bt = t + tw;                          // [-16, 79]
#pragma unroll
    for (int k = 0; k < KR; k++) {
        const int h = h0 + rg + 4 * k;
        float* orow = opl + (size_t)h * NW;
        if ((padMask >> k) & 1u) {
#pragma unroll
            for (int i = 0; i < 4; i++) orow[t + 64 * i] = 0.0f;
            continue;
        }
        const bool rowInCut = (h >= rcx0) && (h <= rcx1);
        const float* srow = s[rg + 4 * k];
#pragma unroll
        for (int i = 0; i < 4; i++) {
            const int w = t + 64 * i;
            int idx = bt + 64 * i;                  // [-16, 271]
            if (idx < 0)            idx += (NW - 1);
            else if (idx >= NW - 1) idx -= (NW - 1);
            const int fIdx = flipOff + flipSign * idx;   // [0,255]
            float val = fmaf(srow[fIdx], cm, ad);
            if (rowInCut && (unsigned)(w - cy0) <= (unsigned)cySpan) val = 0.0f;
            orow[w] = val;
        }
    }
}

extern "C" void kernel_launch(void* const* d_in, const int* in_sizes, int n_in,
                              void* d_out, int out_size)
{
    (void)in_sizes; (void)n_in; (void)out_size;
    const float* x          = (const float*)d_in[0];
    const float* p          = (const float*)d_in[1];
    const float* flip_u     = (const float*)d_in[2];
    const float* bright_n   = (const float*)d_in[3];
    const float* bright_u   = (const float*)d_in[4];
    const float* contrast_n = (const float*)d_in[5];
    const float* contrast_u = (const float*)d_in[6];
    const int*   trans_h    = (const int*)d_in[7];
    const int*   trans_w    = (const int*)d_in[8];
    const float* trans_u    = (const float*)d_in[9];
    const int*   cut_ox     = (const int*)d_in[10];
    const int*   cut_oy     = (const int*)d_in[11];
    const float* cut_u      = (const float*)d_in[12];
    float*       out        = (float*)d_out;

    const dim3 grid(NB * NC * (NH / RPB));
    const dim3 block(256);
    diffaug_kernel<<<grid, block>>>(x, p, flip_u, bright_n, bright_u,
                                    contrast_n, contrast_u, trans_h, trans_w,
                                    trans_u, cut_ox, cut_oy, cut_u, out);
}

// round 15
// speedup vs baseline: 1.1092x; 1.0104x over previous
#include <cuda_runtime.h>
#include <cstdint>

#define NB 64
#define NC 3
#define NH 256
#define NW 256
#define RPB 16                      // rows per block
#define KR 4                        // rows per thread

__device__ __forceinline__ void cpasync16(unsigned saddr, const void* gptr) {
    asm volatile("cp.async.cg.shared.global [%0], [%1], 16;\n" :: "r"(saddr), "l"(gptr));
}

__global__ __launch_bounds__(256)
void diffaug_kernel(const float* __restrict__ x,
                    const float* __restrict__ p_,
                    const float* __restrict__ flip_u,
                    const float* __restrict__ bright_n,
                    const float* __restrict__ bright_u,
                    const float* __restrict__ contrast_n,
                    const float* __restrict__ contrast_u,
                    const int*   __restrict__ trans_h,
                    const int*   __restrict__ trans_w,
                    const float* __restrict__ trans_u,
                    const int*   __restrict__ cut_ox,
                    const int*   __restrict__ cut_oy,
                    const float* __restrict__ cut_u,
                    float* __restrict__ out)
{
    __shared__ __align__(16) float s[RPB][256];   // raw (unflipped) staged rows

    const int blk  = blockIdx.x;
    const int b    = blk / (NC * (NH / RPB));
    const int rem  = blk % (NC * (NH / RPB));
    const int c    = rem / (NH / RPB);
    const int slab = rem % (NH / RPB);
    const int h0   = slab * RPB;

    // ---- per-batch params, loaded uniformly by every thread (no barrier) ----
    const float p    = __ldg(p_);
    const bool  flip = __ldg(flip_u + b) < 0.5f * p;
    const float ba   = (__ldg(bright_u  + b) < p) ? __ldg(bright_n  + b) * 0.2f : 0.0f;
    const float cm   = (__ldg(contrast_u + b) < p) ? exp2f(__ldg(contrast_n + b) * 0.5f) : 1.0f;
    const float ad   = ba * cm;
    const bool  doTrans = __ldg(trans_u + b) < p;
    const int   th_off  = __ldg(trans_h + b) + 1;
    const int   tw      = __ldg(trans_w + b);
    const bool  doCut   = __ldg(cut_u + b) < p;
    const int   ox = __ldg(cut_ox + b), oy = __ldg(cut_oy + b);
    const int   rcx0 = doCut ? max(0, ox - 64)      : (NH + 1);
    const int   rcx1 = doCut ? min(NH - 1, ox + 63) : -1;
    const int   cy0  = max(0, oy - 64);
    const int   cySpan = min(NW - 1, oy + 63) - cy0;

    const int rg = (int)(threadIdx.x >> 6);        // 0..3 row group
    const int t  = (int)(threadIdx.x & 63);        // 0..63
    const int j4 = 4 * t;

    const size_t plane = (size_t)(b * NC + c) * (NH * NW);
    const float* xpl = x + plane;
    float*       opl = out + plane;

    const int gj = flip ? (252 - j4) : j4;

    if (!doTrans) {
        // ---------- Path A: barrier-free vectorized copy (+optional mirror), MLP=4 ----------
        float4 v[KR];
#pragma unroll
        for (int k = 0; k < KR; k++) {
            v[k] = *reinterpret_cast<const float4*>(xpl + (size_t)(h0 + rg + 4 * k) * NW + gj);
        }
#pragma unroll
        for (int k = 0; k < KR; k++) {
            const int h = h0 + rg + 4 * k;
            float a0, a1, a2, a3;
            if (flip) { a0 = v[k].w; a1 = v[k].z; a2 = v[k].y; a3 = v[k].x; }
            else      { a0 = v[k].x; a1 = v[k].y; a2 = v[k].z; a3 = v[k].w; }
            a0 = fmaf(a0, cm, ad); a1 = fmaf(a1, cm, ad);
            a2 = fmaf(a2, cm, ad); a3 = fmaf(a3, cm, ad);
            if (h >= rcx0 && h <= rcx1) {
                if ((unsigned)(j4     - cy0) <= (unsigned)cySpan) a0 = 0.0f;
                if ((unsigned)(j4 + 1 - cy0) <= (unsigned)cySpan) a1 = 0.0f;
                if ((unsigned)(j4 + 2 - cy0) <= (unsigned)cySpan) a2 = 0.0f;
                if ((unsigned)(j4 + 3 - cy0) <= (unsigned)cySpan) a3 = 0.0f;
            }
            *reinterpret_cast<float4*>(opl + (size_t)h * NW + j4) =
                make_float4(a0, a1, a2, a3);
        }
        return;
    }

    // ---------- Path B: raw cp.async staging; 64-thread named barrier per row-group ----------
    unsigned padMask = 0;
#pragma unroll
    for (int k = 0; k < KR; k++) {
        int gh = (h0 + rg + 4 * k) + th_off;
        gh = min(max(gh, 0), NH + 1);
        const bool pad = (gh == 0) || (gh == NH + 1);
        padMask |= (unsigned)pad << k;
        const int srcH = min(max(gh - 1, 0), NH - 1);
        if (!pad) {
            const unsigned saddr =
                (unsigned)__cvta_generic_to_shared(&s[rg + 4 * k][j4]);
            cpasync16(saddr, xpl + (size_t)srcH * NW + j4);
        }
    }
    asm volatile("cp.async.commit_group;\n");
    asm volatile("cp.async.wait_group 0;\n" ::: "memory");
    // rows rg+4k are staged and consumed exclusively by this 64-thread row group
    asm volatile("bar.sync %0, 64;" :: "r"(rg + 1) : "memory");

    // consumer: out[w] = x_raw[255 - gw] if flip else x_raw[gw], gw=(w+tw) mod 255
    // fIdx depends only on i -> hoisted out of the k loop.
    const int flipOff  = flip ? 255 : 0;
    const int flipSign = flip ? -1 : 1;
    int fIdx[4];
#pragma unroll
    for (int i = 0; i < 4; i++) {
        int idx = t + tw + 64 * i;                  // [-16, 271]
        if (idx < 0)            idx += (NW - 1);
        else if (idx >= NW - 1) idx -= (NW - 1);
        fIdx[i] = flipOff + flipSign * idx;         // [0, 255]
    }

#pragma unroll
    for (int k = 0; k < KR; k++) {
        const int h = h0 + rg + 4 * k;
        float* orow = opl + (size_t)h * NW;
        if ((padMask >> k) & 1u) {
            *reinterpret_cast<float4*>(orow + j4) = make_float4(0.f, 0.f, 0.f, 0.f);
            continue;
        }
        const bool rowInCut = (h >= rcx0) && (h <= rcx1);
        const float* srow = s[rg + 4 * k];
#pragma unroll
        for (int i = 0; i < 4; i++) {
            const int w = t + 64 * i;
            float val = fmaf(srow[fIdx[i]], cm, ad);
            if (rowInCut && (unsigned)(w - cy0) <= (unsigned)cySpan) val = 0.0f;
            orow[w] = val;
        }
    }
}

extern "C" void kernel_launch(void* const* d_in, const int* in_sizes, int n_in,
                              void* d_out, int out_size)
{
    (void)in_sizes; (void)n_in; (void)out_size;
    const float* x          = (const float*)d_in[0];
    const float* p          = (const float*)d_in[1];
    const float* flip_u     = (const float*)d_in[2];
    const float* bright_n   = (const float*)d_in[3];
    const float* bright_u   = (const float*)d_in[4];
    const float* contrast_n = (const float*)d_in[5];
    const float* contrast_u = (const float*)d_in[6];
    const int*   trans_h    = (const int*)d_in[7];
    const int*   trans_w    = (const int*)d_in[8];
    const float* trans_u    = (const float*)d_in[9];
    const int*   cut_ox     = (const int*)d_in[10];
    const int*   cut_oy     = (const int*)d_in[11];
    const float* cut_u      = (const float*)d_in[12];
    float*       out        = (float*)d_out;

    const dim3 grid(NB * NC * (NH / RPB));
    const dim3 block(256);
    diffaug_kernel<<<grid, block>>>(x, p, flip_u, bright_n, bright_u,
                                    contrast_n, contrast_u, trans_h, trans_w,
                                    trans_u, cut_ox, cut_oy, cut_u, out);
}

// round 17
// speedup vs baseline: 1.1679x; 1.0529x over previous
#include <cuda_runtime.h>
#include <cstdint>

#define NB 64
#define NC 3
#define NH 256
#define NW 256
#define RPB 16                      // rows per block
#define KR 4                        // rows per thread

__device__ __forceinline__ void cpasync16(unsigned saddr, const void* gptr) {
    asm volatile("cp.async.cg.shared.global [%0], [%1], 16;\n" :: "r"(saddr), "l"(gptr));
}

__global__ __launch_bounds__(256)
void diffaug_kernel(const float* __restrict__ x,
                    const float* __restrict__ p_,
                    const float* __restrict__ flip_u,
                    const float* __restrict__ bright_n,
                    const float* __restrict__ bright_u,
                    const float* __restrict__ contrast_n,
                    const float* __restrict__ contrast_u,
                    const int*   __restrict__ trans_h,
                    const int*   __restrict__ trans_w,
                    const float* __restrict__ trans_u,
                    const int*   __restrict__ cut_ox,
                    const int*   __restrict__ cut_oy,
                    const float* __restrict__ cut_u,
                    float* __restrict__ out)
{
    __shared__ __align__(16) float s[RPB][256];   // raw (unflipped) staged rows

    const int blk  = blockIdx.x;
    const int b    = blk / (NC * (NH / RPB));
    const int rem  = blk % (NC * (NH / RPB));
    const int c    = rem / (NH / RPB);
    const int slab = rem % (NH / RPB);
    const int h0   = slab * RPB;

    // ---- per-batch params, loaded uniformly by every thread (no barrier) ----
    const float p    = __ldg(p_);
    const bool  flip = __ldg(flip_u + b) < 0.5f * p;
    const float ba   = (__ldg(bright_u  + b) < p) ? __ldg(bright_n  + b) * 0.2f : 0.0f;
    const float cm   = (__ldg(contrast_u + b) < p) ? exp2f(__ldg(contrast_n + b) * 0.5f) : 1.0f;
    const float ad   = ba * cm;
    const bool  doTrans = __ldg(trans_u + b) < p;
    const int   th_off  = __ldg(trans_h + b) + 1;
    const int   tw      = __ldg(trans_w + b);
    const bool  doCut   = __ldg(cut_u + b) < p;
    const int   ox = __ldg(cut_ox + b), oy = __ldg(cut_oy + b);
    const int   rcx0 = doCut ? max(0, ox - 64)      : (NH + 1);
    const int   rcx1 = doCut ? min(NH - 1, ox + 63) : -1;
    const int   cy0  = max(0, oy - 64);
    const int   cySpan = min(NW - 1, oy + 63) - cy0;

    const int rg = (int)(threadIdx.x >> 6);        // 0..3 row group
    const int t  = (int)(threadIdx.x & 63);        // 0..63
    const int j4 = 4 * t;

    const size_t plane = (size_t)(b * NC + c) * (NH * NW);
    const float* xpl = x + plane;
    float*       opl = out + plane;

    const int gj = flip ? (252 - j4) : j4;

    if (!doTrans) {
        // ---------- Path A: barrier-free vectorized copy (+optional mirror), MLP=4 ----------
        float4 v[KR];
#pragma unroll
        for (int k = 0; k < KR; k++) {
            v[k] = *reinterpret_cast<const float4*>(xpl + (size_t)(h0 + rg + 4 * k) * NW + gj);
        }
#pragma unroll
        for (int k = 0; k < KR; k++) {
            const int h = h0 + rg + 4 * k;
            float a0, a1, a2, a3;
            if (flip) { a0 = v[k].w; a1 = v[k].z; a2 = v[k].y; a3 = v[k].x; }
            else      { a0 = v[k].x; a1 = v[k].y; a2 = v[k].z; a3 = v[k].w; }
            a0 = fmaf(a0, cm, ad); a1 = fmaf(a1, cm, ad);
            a2 = fmaf(a2, cm, ad); a3 = fmaf(a3, cm, ad);
            if (h >= rcx0 && h <= rcx1) {
                if ((unsigned)(j4     - cy0) <= (unsigned)cySpan) a0 = 0.0f;
                if ((unsigned)(j4 + 1 - cy0) <= (unsigned)cySpan) a1 = 0.0f;
                if ((unsigned)(j4 + 2 - cy0) <= (unsigned)cySpan) a2 = 0.0f;
                if ((unsigned)(j4 + 3 - cy0) <= (unsigned)cySpan) a3 = 0.0f;
            }
            *reinterpret_cast<float4*>(opl + (size_t)h * NW + j4) =
                make_float4(a0, a1, a2, a3);
        }
        return;
    }

    // ---------- Path B: raw cp.async staging, single block barrier ----------
    unsigned padMask = 0;
#pragma unroll
    for (int k = 0; k < KR; k++) {
        int gh = (h0 + rg + 4 * k) + th_off;
        gh = min(max(gh, 0), NH + 1);
        const bool pad = (gh == 0) || (gh == NH + 1);
        padMask |= (unsigned)pad << k;
        const int srcH = min(max(gh - 1, 0), NH - 1);
        if (!pad) {
            const unsigned saddr =
                (unsigned)__cvta_generic_to_shared(&s[rg + 4 * k][j4]);
            cpasync16(saddr, xpl + (size_t)srcH * NW + j4);
        }
    }
    asm volatile("cp.async.commit_group;\n");
    asm volatile("cp.async.wait_group 0;\n" ::: "memory");
    __syncthreads();

    // consumer: out[w] = x_raw[255 - gw] if flip else x_raw[gw], gw=(w+tw) mod 255
    // fIdx depends only on i -> hoisted out of the k loop.
    const int flipOff  = flip ? 255 : 0;
    const int flipSign = flip ? -1 : 1;
    int fIdx[4];
#pragma unroll
    for (int i = 0; i < 4; i++) {
        int idx = t + tw + 64 * i;                  // [-16, 271]
        if (idx < 0)            idx += (NW - 1);
        else if (idx >= NW - 1) idx -= (NW - 1);
        fIdx[i] = flipOff + flipSign * idx;         // [0, 255]
    }

#pragma unroll
    for (int k = 0; k < KR; k++) {
        const int h = h0 + rg + 4 * k;
        float* orow = opl + (size_t)h * NW;
        if ((padMask >> k) & 1u) {
            *reinterpret_cast<float4*>(orow + j4) = make_float4(0.f, 0.f, 0.f, 0.f);
            continue;
        }
        const bool rowInCut = (h >= rcx0) && (h <= rcx1);
        const float* srow = s[rg + 4 * k];
#pragma unroll
        for (int i = 0; i < 4; i++) {
            const int w = t + 64 * i;
            float val = fmaf(srow[fIdx[i]], cm, ad);
            if (rowInCut && (unsigned)(w - cy0) <= (unsigned)cySpan) val = 0.0f;
            orow[w] = val;
        }
    }
}

extern "C" void kernel_launch(void* const* d_in, const int* in_sizes, int n_in,
                              void* d_out, int out_size)
{
    (void)in_sizes; (void)n_in; (void)out_size;
    const float* x          = (const float*)d_in[0];
    const float* p          = (const float*)d_in[1];
    const float* flip_u     = (const float*)d_in[2];
    const float* bright_n   = (const float*)d_in[3];
    const float* bright_u   = (const float*)d_in[4];
    const float* contrast_n = (const float*)d_in[5];
    const float* contrast_u = (const float*)d_in[6];
    const int*   trans_h    = (const int*)d_in[7];
    const int*   trans_w    = (const int*)d_in[8];
    const float* trans_u    = (const float*)d_in[9];
    const int*   cut_ox     = (const int*)d_in[10];
    const int*   cut_oy     = (const int*)d_in[11];
    const float* cut_u      = (const float*)d_in[12];
    float*       out        = (float*)d_out;

    const dim3 grid(NB * NC * (NH / RPB));
    const dim3 block(256);
    diffaug_kernel<<<grid, block>>>(x, p, flip_u, bright_n, bright_u,
                                    contrast_n, contrast_u, trans_h, trans_w,
                                    trans_u, cut_ox, cut_oy, cut_u, out);
}